// round 2
// baseline (speedup 1.0000x reference)
#include <cuda_runtime.h>
#include <cuda_bf16.h>
#include <cstdint>

// y_t = d*y_{t-1} + x_t   per channel, y_{-1} = 0  (so y_0 = x_0)
// x: [BSZ=8, SEQ=4096, CH=1024] fp32, d: [CH] fp32, out same shape as x.
//
// One block per (batch, 32-channel group) column = 256 blocks.
// Block = 256 threads = NSUB(8) t-subtiles x 32 channels.
// 16 chunks of 256 timesteps; per chunk:
//   - each thread loads TSUB(32) values (coalesced 128B/warp), scans them
//     serially in registers with zero initial condition,
//   - warp 0 does the 8-step cross-subtile affine scan per channel
//     (multiplier is the constant d^32) via shared memory, carrying the
//     per-channel state across chunks in a register,
//   - every thread applies y_i = ylocal_i + d^(i+1) * prefix and stores.
// Next chunk's loads are prefetched into a second register buffer before the
// barriers so DRAM latency overlaps scan + sync + correction work.

#define BSZ    8
#define SEQ    4096
#define CH     1024
#define TSUB   32
#define NSUB   8
#define NTHR   (NSUB * 32)          // 256
#define CHUNK  (TSUB * NSUB)        // 256
#define NCHUNK (SEQ / CHUNK)        // 16
#define CGRPS  (CH / 32)            // 32 channel groups per batch

__global__ __launch_bounds__(NTHR)
void cummulsum_kernel(const float* __restrict__ x,
                      const float* __restrict__ d,
                      float* __restrict__ y)
{
    __shared__ float subAgg[NSUB][32];
    __shared__ float pfx[NSUB][32];

    const int tid  = threadIdx.x;
    const int lane = tid & 31;
    const int s    = tid >> 5;          // subtile index 0..7
    const int b    = blockIdx.x >> 5;   // batch 0..7
    const int cg   = blockIdx.x & 31;   // channel group 0..31
    const int c    = cg * 32 + lane;    // channel

    const float dc = __ldg(d + c);
    // dT = dc^TSUB = dc^32 via 5 squarings
    float dT = dc * dc;   // ^2
    dT = dT * dT;         // ^4
    dT = dT * dT;         // ^8
    dT = dT * dT;         // ^16
    dT = dT * dT;         // ^32

    const size_t colBase = ((size_t)b * SEQ) * CH + (size_t)c;
    const float* xp = x + colBase + (size_t)(s * TSUB) * CH;
    float*       yp = y + colBase + (size_t)(s * TSUB) * CH;

    float carry = 0.0f;   // running per-channel state (meaningful in warp 0)

    float xa[TSUB];
    float xb[TSUB];

    // Prologue: load chunk 0
    #pragma unroll
    for (int i = 0; i < TSUB; i++) xa[i] = xp[(size_t)i * CH];

    #pragma unroll 2
    for (int k = 0; k < NCHUNK; k++) {
        // Prefetch next chunk: independent of everything below; the loads
        // fly during the local scan + barriers + cross-subtile scan.
        const float* xpn = xp + (size_t)CHUNK * CH;
        if (k + 1 < NCHUNK) {
            #pragma unroll
            for (int i = 0; i < TSUB; i++) xb[i] = xpn[(size_t)i * CH];
        }

        // Local serial scan in place (zero initial condition)
        #pragma unroll
        for (int i = 1; i < TSUB; i++) xa[i] = fmaf(dc, xa[i - 1], xa[i]);

        subAgg[s][lane] = xa[TSUB - 1];
        __syncthreads();

        if (s == 0) {
            // Cross-subtile affine scan; each lane handles its channel.
            float agg[NSUB];
            #pragma unroll
            for (int j = 0; j < NSUB; j++) agg[j] = subAgg[j][lane];
            float P = carry;
            #pragma unroll
            for (int j = 0; j < NSUB; j++) {
                pfx[j][lane] = P;             // state entering subtile j
                P = fmaf(dT, P, agg[j]);      // advance past subtile j
            }
            carry = P;                         // state entering next chunk
        }
        __syncthreads();

        // Apply correction and store: y_i = ylocal_i + dc^(i+1) * P
        const float P = pfx[s][lane];
        float f = dc;
        #pragma unroll
        for (int i = 0; i < TSUB; i++) {
            yp[(size_t)i * CH] = fmaf(f, P, xa[i]);
            f *= dc;
        }

        // Rotate buffers (register renames under the unrolled outer loop)
        #pragma unroll
        for (int i = 0; i < TSUB; i++) xa[i] = xb[i];

        xp += (size_t)CHUNK * CH;
        yp += (size_t)CHUNK * CH;
    }
}

extern "C" void kernel_launch(void* const* d_in, const int* in_sizes, int n_in,
                              void* d_out, int out_size)
{
    const float* x = (const float*)d_in[0];
    const float* d = (const float*)d_in[1];
    float*       y = (float*)d_out;
    (void)in_sizes; (void)n_in; (void)out_size;

    cummulsum_kernel<<<BSZ * CGRPS, NTHR>>>(x, d, y);
}

// round 3
// speedup vs baseline: 1.0473x; 1.0473x over previous
#include <cuda_runtime.h>
#include <cuda_bf16.h>
#include <cstdint>

// y_t = d*y_{t-1} + x_t   per channel, y_{-1} = 0  (so y_0 = x_0)
// x: [BSZ=8, SEQ=4096, CH=1024] fp32, d: [CH] fp32, out same shape as x.
//
// One block per (batch, 32-channel group) column = 256 blocks.
// Block = 256 threads = NSUB(8) t-subtiles x 32 channels.
// TSUB=16 (was 32) so the xa/xb double buffer is 32 regs, letting
// __launch_bounds__(256, 2) place 2 blocks/SM: all 256 blocks co-resident
// in a single wave (n_conc = 296), doubling per-SM memory-level parallelism.
//
// Per chunk of 128 timesteps:
//   - each thread loads TSUB values (coalesced 128B/warp), scans them
//     serially in registers with zero initial condition,
//   - warp 0 does the 8-step cross-subtile affine scan per channel
//     (multiplier is the constant d^16) via shared memory, carrying the
//     per-channel state across chunks in a register,
//   - every thread applies y_i = ylocal_i + d^(i+1) * prefix and stores.
// Next chunk's loads are prefetched into the second register buffer before
// the barriers so DRAM latency overlaps scan + sync + correction work.

#define BSZ    8
#define SEQ    4096
#define CH     1024
#define TSUB   16
#define NSUB   8
#define NTHR   (NSUB * 32)          // 256
#define CHUNK  (TSUB * NSUB)        // 128
#define NCHUNK (SEQ / CHUNK)        // 32
#define CGRPS  (CH / 32)            // 32 channel groups per batch

__global__ __launch_bounds__(NTHR, 2)
void cummulsum_kernel(const float* __restrict__ x,
                      const float* __restrict__ d,
                      float* __restrict__ y)
{
    __shared__ float subAgg[NSUB][32];
    __shared__ float pfx[NSUB][32];

    const int tid  = threadIdx.x;
    const int lane = tid & 31;
    const int s    = tid >> 5;          // subtile index 0..7
    const int b    = blockIdx.x >> 5;   // batch 0..7
    const int cg   = blockIdx.x & 31;   // channel group 0..31
    const int c    = cg * 32 + lane;    // channel

    const float dc = __ldg(d + c);
    // dT = dc^TSUB = dc^16 via 4 squarings
    float dT = dc * dc;   // ^2
    dT = dT * dT;         // ^4
    dT = dT * dT;         // ^8
    dT = dT * dT;         // ^16

    const size_t colBase = ((size_t)b * SEQ) * CH + (size_t)c;
    const float* xp = x + colBase + (size_t)(s * TSUB) * CH;
    float*       yp = y + colBase + (size_t)(s * TSUB) * CH;

    float carry = 0.0f;   // running per-channel state (meaningful in warp 0)

    float xa[TSUB];
    float xb[TSUB];

    // Prologue: load chunk 0
    #pragma unroll
    for (int i = 0; i < TSUB; i++) xa[i] = xp[(size_t)i * CH];

    #pragma unroll 2
    for (int k = 0; k < NCHUNK; k++) {
        // Prefetch next chunk: independent of everything below; the loads
        // fly during the local scan + barriers + cross-subtile scan.
        const float* xpn = xp + (size_t)CHUNK * CH;
        if (k + 1 < NCHUNK) {
            #pragma unroll
            for (int i = 0; i < TSUB; i++) xb[i] = xpn[(size_t)i * CH];
        }

        // Local serial scan in place (zero initial condition)
        #pragma unroll
        for (int i = 1; i < TSUB; i++) xa[i] = fmaf(dc, xa[i - 1], xa[i]);

        subAgg[s][lane] = xa[TSUB - 1];
        __syncthreads();

        if (s == 0) {
            // Cross-subtile affine scan; each lane handles its channel.
            float agg[NSUB];
            #pragma unroll
            for (int j = 0; j < NSUB; j++) agg[j] = subAgg[j][lane];
            float P = carry;
            #pragma unroll
            for (int j = 0; j < NSUB; j++) {
                pfx[j][lane] = P;             // state entering subtile j
                P = fmaf(dT, P, agg[j]);      // advance past subtile j
            }
            carry = P;                         // state entering next chunk
        }
        __syncthreads();

        // Apply correction and store: y_i = ylocal_i + dc^(i+1) * P
        const float P = pfx[s][lane];
        float f = dc;
        #pragma unroll
        for (int i = 0; i < TSUB; i++) {
            yp[(size_t)i * CH] = fmaf(f, P, xa[i]);
            f *= dc;
        }

        // Rotate buffers (register renames under the unrolled outer loop)
        #pragma unroll
        for (int i = 0; i < TSUB; i++) xa[i] = xb[i];

        xp += (size_t)CHUNK * CH;
        yp += (size_t)CHUNK * CH;
    }
}

extern "C" void kernel_launch(void* const* d_in, const int* in_sizes, int n_in,
                              void* d_out, int out_size)
{
    const float* x = (const float*)d_in[0];
    const float* d = (const float*)d_in[1];
    float*       y = (float*)d_out;
    (void)in_sizes; (void)n_in; (void)out_size;

    cummulsum_kernel<<<BSZ * CGRPS, NTHR>>>(x, d, y);
}